// round 7
// baseline (speedup 1.0000x reference)
#include <cuda_runtime.h>
#include <math.h>
#include <stdint.h>

#define B 64
#define H 128
#define E 128
#define NL 4
#define S 8192
#define V 50257
#define FOURH 512
#define CHUNKS 128      // S / ROWS
#define ROWS 64
#define NWORK 1024      // copy/flash worker blocks
#define UPB 8           // units per worker (NWORK*UPB == CHUNKS*B)
#define UNIT_BYTES 32768

#define SZ_LOGITS (B*V)
#define OFF_C  (SZ_LOGITS)
#define OFF_H  (OFF_C + NL*B*H)
#define OFF_ATTN (OFF_H + NL*B*H)

// dynamic smem layout (worker view)
#define SM_BUF0   0
#define SM_BUF1   32768
#define SM_MBAR   65536          // 2 x u64
#define SM_FLASH  65552          // acc[8][128] f32, m[8], l[8]
#define SMEM_BYTES (65552 + 8*H*4 + 64)

typedef unsigned long long ull;

// ---------------- device scratch (no allocations allowed) ----------------
__device__ __align__(16) float g_x[B*H];
__device__ __align__(16) float g_r[B*H];
__device__ float g_cK[B];
__device__ float g_pm[B*CHUNKS];
__device__ float g_pl[B*CHUNKS];
__device__ __align__(16) float g_pacc[B*CHUNKS*H];
__device__ __align__(16) float g_hln[B*H];
__device__ int g_done = 0;

__device__ __forceinline__ float warp_sum(float v) {
#pragma unroll
    for (int o = 16; o > 0; o >>= 1) v += __shfl_xor_sync(0xffffffffu, v, o);
    return v;
}
__device__ __forceinline__ float sigf(float x) { return 1.f / (1.f + __expf(-x)); }

__device__ __forceinline__ ull fma2(ull a, ull b, ull c) {
    ull d;
    asm("fma.rn.f32x2 %0, %1, %2, %3;" : "=l"(d) : "l"(a), "l"(b), "l"(c));
    return d;
}
__device__ __forceinline__ ull bcast2(float f) {
    ull d;
    asm("mov.b64 %0, {%1, %1};" : "=l"(d) : "f"(f));
    return d;
}

// ---------------- TMA / mbarrier primitives -------------------------------
__device__ __forceinline__ void mbar_init(uint32_t mbar, uint32_t cnt) {
    asm volatile("mbarrier.init.shared.b64 [%0], %1;" :: "r"(mbar), "r"(cnt) : "memory");
}
__device__ __forceinline__ void mbar_expect_tx(uint32_t mbar, uint32_t tx) {
    asm volatile("mbarrier.arrive.expect_tx.shared.b64 _, [%0], %1;"
                 :: "r"(mbar), "r"(tx) : "memory");
}
__device__ __forceinline__ void mbar_wait(uint32_t mbar, uint32_t parity) {
    asm volatile(
        "{\n\t.reg .pred P;\n"
        "W%=:\n\t"
        "mbarrier.try_wait.parity.shared.b64 P, [%0], %1;\n\t"
        "@!P bra W%=;\n\t}"
        :: "r"(mbar), "r"(parity) : "memory");
}
__device__ __forceinline__ void bulk_g2s(uint32_t smem, const void* g, uint32_t bytes, uint32_t mbar) {
    asm volatile("cp.async.bulk.shared::cta.global.mbarrier::complete_tx::bytes [%0], [%1], %2, [%3];"
                 :: "r"(smem), "l"(g), "r"(bytes), "r"(mbar) : "memory");
}
__device__ __forceinline__ void bulk_s2g(void* g, uint32_t smem, uint32_t bytes) {
    asm volatile("cp.async.bulk.global.shared::cta.bulk_group [%0], [%1], %2;"
                 :: "l"(g), "r"(smem), "r"(bytes) : "memory");
    asm volatile("cp.async.bulk.commit_group;" ::: "memory");
}
__device__ __forceinline__ void fence_async() {
    asm volatile("fence.proxy.async.shared::cta;" ::: "memory");
}

// -------- LSTM smem (overlays worker smem at offset 0) --------------------
struct LstmSmem {
    ull xs2[2][H];
    ull hs2[2][H];
    float gp[2][2][FOURH];
    float qs[2][H];
};

__device__ void lstm_body(
    LstmSmem& sm, int b0,
    const int* __restrict__ token_id, const float* __restrict__ c0,
    const float* __restrict__ h0, const float* __restrict__ emb,
    const float* __restrict__ Wi, const float* __restrict__ Uh,
    const float* __restrict__ bL, const float* __restrict__ Wq,
    const float* __restrict__ bq, const float* __restrict__ Wk,
    const float* __restrict__ bk, float* __restrict__ out)
{
    int tid = threadIdx.x;

    for (int idx = tid; idx < 2*H; idx += 256) {
        int bb = idx >> 7, i = idx & 127;
        float v = emb[(size_t)token_id[b0+bb]*E + i];
        sm.xs2[bb][i] = bcast2(v);
    }

    int khalf = tid >> 7;
    int tc = tid & 127;
    int cbase = tc * 4;

    for (int l = 0; l < NL; l++) {
        for (int idx = tid; idx < 2*H; idx += 256) {
            int bb = idx >> 7, i = idx & 127;
            float v = h0[((size_t)l*B + b0 + bb)*H + i];
            sm.hs2[bb][i] = bcast2(v);
        }
        __syncthreads();

        ull a00 = 0, a01 = 0, a10 = 0, a11 = 0;
        const ulonglong2* Wi2 = (const ulonglong2*)(Wi + (size_t)l*E*FOURH);
        const ulonglong2* Uh2 = (const ulonglong2*)(Uh + (size_t)l*H*FOURH);
        int k0 = khalf * 64;
#pragma unroll 4
        for (int k = k0; k < k0 + 64; k++) {
            ulonglong2 w = Wi2[k*(FOURH/4) + tc];
            ulonglong2 u = Uh2[k*(FOURH/4) + tc];
            ull x0 = sm.xs2[0][k], x1 = sm.xs2[1][k];
            ull hh0 = sm.hs2[0][k], hh1 = sm.hs2[1][k];
            a00 = fma2(w.x, x0, a00);  a01 = fma2(w.y, x0, a01);
            a00 = fma2(u.x, hh0, a00); a01 = fma2(u.y, hh0, a01);
            a10 = fma2(w.x, x1, a10);  a11 = fma2(w.y, x1, a11);
            a10 = fma2(u.x, hh1, a10); a11 = fma2(u.y, hh1, a11);
        }
        *(ull*)&sm.gp[khalf][0][cbase]   = a00;
        *(ull*)&sm.gp[khalf][0][cbase+2] = a01;
        *(ull*)&sm.gp[khalf][1][cbase]   = a10;
        *(ull*)&sm.gp[khalf][1][cbase+2] = a11;
        __syncthreads();

        {
            int bb = tid >> 7, i = tid & 127;
            const float* bb_l = bL + l*FOURH;
            float ig = sm.gp[0][bb][i]       + sm.gp[1][bb][i]       + bb_l[i];
            float fg = sm.gp[0][bb][128 + i] + sm.gp[1][bb][128 + i] + bb_l[128 + i];
            float gg = sm.gp[0][bb][256 + i] + sm.gp[1][bb][256 + i] + bb_l[256 + i];
            float og = sm.gp[0][bb][384 + i] + sm.gp[1][bb][384 + i] + bb_l[384 + i];
            size_t ofs = ((size_t)l*B + b0 + bb)*H + i;
            float cprev = c0[ofs];
            float cn = sigf(fg)*cprev + sigf(ig)*tanhf(gg);
            float hn = sigf(og)*tanhf(cn);
            out[OFF_C + ofs] = cn;
            out[OFF_H + ofs] = hn;
            sm.xs2[bb][i] = bcast2(hn);
        }
    }
    __syncthreads();

    for (int idx = tid; idx < 2*H; idx += 256) {
        int bb = idx >> 7, i = idx & 127;
        g_x[(b0+bb)*H + i] = ((const float2*)&sm.xs2[bb][i])->x;
    }

    {
        int bb = tid >> 7, j = tid & 127;
        float acc = bq[j];
#pragma unroll 8
        for (int i = 0; i < H; i++)
            acc += ((const float2*)&sm.xs2[bb][i])->x * Wq[i*H + j];
        sm.qs[bb][j] = acc;
    }
    __syncthreads();

    int wid = tid >> 5, lane = tid & 31;
    for (int row = wid; row < 2*H; row += 8) {
        int bb = row >> 7, i = row & 127;
        float4 wv = ((const float4*)(Wk + (size_t)i*H))[lane];
        float4 qv = ((const float4*)sm.qs[bb])[lane];
        float d = wv.x*qv.x + wv.y*qv.y + wv.z*qv.z + wv.w*qv.w;
        d = warp_sum(d);
        if (lane == 0) g_r[(b0+bb)*H + i] = d;
    }
    if (wid < 2) {
        int bb = wid;
        float p = 0.f;
        for (int j = lane; j < H; j += 32) p += bk[j] * sm.qs[bb][j];
        p = warp_sum(p);
        if (lane == 0) g_cK[b0+bb] = p;
    }
}

// ==== MEGA: 32 LSTM blocks + 1024 TMA-pipelined copy/flash workers ========
// Worker w handles units w, w+1024, ..., w+7*1024 (inactive chunks first).
// Each unit = 32KB tile (one chunk x one batch): bulk-TMA gmem->smem,
// splice x at step row, bulk-TMA smem->gmem, flash partials from smem.
__global__ __launch_bounds__(256) void k_mega(
    const float* __restrict__ attn_mem, const int* __restrict__ step_p,
    const int* __restrict__ token_id, const float* __restrict__ c0,
    const float* __restrict__ h0, const float* __restrict__ emb,
    const float* __restrict__ Wi, const float* __restrict__ Uh,
    const float* __restrict__ bL, const float* __restrict__ Wq,
    const float* __restrict__ bq, const float* __restrict__ Wk,
    const float* __restrict__ bk, float* __restrict__ out)
{
    extern __shared__ __align__(16) char smem_raw[];

    int id = blockIdx.x;
    int tid = threadIdx.x, wid = tid >> 5, lane = tid & 31;

    if (id < 32) {
        LstmSmem& ls = *(LstmSmem*)smem_raw;
        lstm_body(ls, id*2, token_id, c0, h0, emb, Wi, Uh, bL, Wq, bq, Wk, bk, out);
        __syncthreads();
        __threadfence();
        if (tid == 0) atomicAdd(&g_done, 1);
        return;
    }

    int w = id - 32;
    int step = *step_p;
    const float scl = 0.08838834764831843f;   // 1/sqrt(128)

    uint32_t sbase = (uint32_t)__cvta_generic_to_shared(smem_raw);
    uint32_t s_mbar = sbase + SM_MBAR;
    float (*fl_acc)[H] = (float(*)[H])(smem_raw + SM_FLASH);
    float* fl_m = (float*)(smem_raw + SM_FLASH + 8*H*4);
    float* fl_l = fl_m + 8;

    if (tid == 0) {
        mbar_init(s_mbar, 1);
        mbar_init(s_mbar + 8, 1);
        fence_async();
    }
    __syncthreads();

    int ph0 = 0, ph1 = 0;
    bool lstm_ready = false;

    // prefetch unit 0
    if (tid == 0) {
        int u = w;
        int b = u & 63, chunk = 127 - (u >> 6);
        const char* srcp = (const char*)attn_mem +
            ((size_t)b*S*H + (size_t)chunk*ROWS*H)*4;
        mbar_expect_tx(s_mbar, UNIT_BYTES);
        bulk_g2s(sbase + SM_BUF0, srcp, UNIT_BYTES, s_mbar);
    }

#pragma unroll 1
    for (int i = 0; i < UPB; i++) {
        int u = w + i*NWORK;
        int b = u & 63;
        int chunk = 127 - (u >> 6);        // inactive (high) chunks first
        int buf = i & 1;
        uint32_t s_buf = sbase + (buf ? SM_BUF1 : SM_BUF0);
        char* bufp = smem_raw + (buf ? SM_BUF1 : SM_BUF0);
        bool active = (chunk*ROWS <= step);

        if (active && !lstm_ready) {
            if (tid == 0) {
                int fv;
                do {
                    asm volatile("ld.global.cg.b32 %0, [%1];" : "=r"(fv) : "l"(&g_done));
                    if (fv < 32) __nanosleep(64);
                } while (fv < 32);
            }
            __syncthreads();
            __threadfence();               // acquire
            lstm_ready = true;
        }

        // wait for this unit's tile
        mbar_wait(s_mbar + buf*8, buf ? ph1 : ph0);
        if (buf) ph1 ^= 1; else ph0 ^= 1;

        // splice x into the step row (k/v for position step is new hidden x)
        int lr = step - chunk*ROWS;
        if (active && lr >= 0 && lr < ROWS && tid < 32) {
            float4 xv;
            const float* xp = g_x + b*H + tid*4;
            xv.x = __ldcg(xp); xv.y = __ldcg(xp+1);
            xv.z = __ldcg(xp+2); xv.w = __ldcg(xp+3);
            *(float4*)(bufp + lr*512 + tid*16) = xv;
        }
        __syncthreads();   // tile + splice visible to all; prior iter fully done

        if (tid == 0) {
            fence_async();                 // order generic splice before async store
            char* dstp = (char*)out +
                ((size_t)OFF_ATTN + (size_t)b*S*H + (size_t)chunk*ROWS*H)*4;
            bulk_s2g(dstp, s_buf, UNIT_BYTES);
            // prefetch next unit into the other buffer
            if (i + 1 < UPB) {
                asm volatile("cp.async.bulk.wait_group.read 1;" ::: "memory");
                int u2 = w + (i+1)*NWORK;
                int b2 = u2 & 63, c2 = 127 - (u2 >> 6);
                const char* srcp2 = (const char*)attn_mem +
                    ((size_t)b2*S*H + (size_t)c2*ROWS*H)*4;
                uint32_t mb2 = s_mbar + ((i+1)&1)*8;
                mbar_expect_tx(mb2, UNIT_BYTES);
                bulk_g2s(sbase + (((i+1)&1) ? SM_BUF1 : SM_BUF0), srcp2, UNIT_BYTES, mb2);
            }
        }

        if (!active) continue;

        // ---- flash partial pass from smem tile ----
        const float4* bp = (const float4*)bufp;
        float4 rf;
        {
            const float* rp = g_r + b*H + lane*4;
            rf.x = __ldcg(rp); rf.y = __ldcg(rp+1); rf.z = __ldcg(rp+2); rf.w = __ldcg(rp+3);
        }
        float cK = __ldcg(&g_cK[b]);
        int rbase = wid*8;                 // local row base
        int gbase = chunk*ROWS + rbase;    // global row base

        float4 v[8];
#pragma unroll
        for (int t = 0; t < 8; t++) v[t] = bp[(rbase+t)*32 + lane];

        float d[8];
#pragma unroll
        for (int t = 0; t < 8; t++)
            d[t] = v[t].x*rf.x + v[t].y*rf.y + v[t].z*rf.z + v[t].w*rf.w;
#pragma unroll
        for (int o = 16; o > 0; o >>= 1) {
#pragma unroll
            for (int t = 0; t < 8; t++)
                d[t] += __shfl_xor_sync(0xffffffffu, d[t], o);
        }

        float m = -INFINITY;
#pragma unroll
        for (int t = 0; t < 8; t++) {
            d[t] = (gbase + t <= step) ? (d[t] + cK) * scl : -INFINITY;
            m = fmaxf(m, d[t]);
        }
        float l = 0.f;
        float4 acc = {0.f, 0.f, 0.f, 0.f};
#pragma unroll
        for (int t = 0; t < 8; t++) {
            float ww = (gbase + t <= step) ? __expf(d[t] - m) : 0.f;
            l += ww;
            acc.x += ww*v[t].x; acc.y += ww*v[t].y;
            acc.z += ww*v[t].z; acc.w += ww*v[t].w;
        }

        __syncthreads();   // WAR guard on fl_* reuse
        ((float4*)fl_acc[wid])[lane] = acc;
        if (lane == 0) { fl_m[wid] = m; fl_l[wid] = l; }
        __syncthreads();

        if (tid < H) {
            float M = fl_m[0];
#pragma unroll
            for (int ww = 1; ww < 8; ww++) M = fmaxf(M, fl_m[ww]);
            float a = 0.f, L = 0.f;
#pragma unroll
            for (int ww = 0; ww < 8; ww++) {
                float e = __expf(fl_m[ww] - M);   // exp(-inf) = 0
                a += fl_acc[ww][tid] * e;
                L += fl_l[ww] * e;
            }
            g_pacc[((size_t)b*CHUNKS + chunk)*H + tid] = a;
            if (tid == 0) { g_pm[b*CHUNKS + chunk] = M; g_pl[b*CHUNKS + chunk] = L; }
        }
    }

    // drain TMA stores before CTA exit (smem dealloc safety)
    if (tid == 0)
        asm volatile("cp.async.bulk.wait_group.read 0;" ::: "memory");
    __syncthreads();
}

// ==== K3: combine partials -> ctx -> mix -> tanh -> LayerNorm ============
__global__ __launch_bounds__(256) void k_reduce_mix(
    const int* __restrict__ step_p,
    const float* __restrict__ Wv, const float* __restrict__ bv,
    const float* __restrict__ Wmix, const float* __restrict__ bmix,
    const float* __restrict__ lns, const float* __restrict__ lnb)
{
    __shared__ float es[CHUNKS];
    __shared__ float red[128];
    __shared__ float part[256];
    __shared__ float cp[H], xsm[H], ctxs[H];

    int b = blockIdx.x;
    int tid = threadIdx.x;
    int t = tid & 127, half = tid >> 7;
    int nact = (*step_p >> 6) + 1;

    if (tid < 128) {
        float pm = (tid < nact) ? g_pm[b*CHUNKS + tid] : -INFINITY;
        red[tid] = pm;
    }
    __syncthreads();
    for (int o = 64; o > 0; o >>= 1) {
        if (tid < o) red[tid] = fmaxf(red[tid], red[tid+o]);
        __syncthreads();
    }
    float M = red[0];
    __syncthreads();

    if (tid < 128) {
        float pm = (tid < nact) ? g_pm[b*CHUNKS + tid] : -INFINITY;
        float pl = (tid < nact) ? g_pl[b*CHUNKS + tid] : 0.f;
        float e = __expf(pm - M);
        es[tid] = e;
        red[tid] = pl * e;
    }
    __syncthreads();
    for (int o = 64; o > 0; o >>= 1) {
        if (tid < o) red[tid] += red[tid+o];
        __syncthreads();
    }
    float L = red[0];
    __syncthreads();

    {
        float a = 0.f;
#pragma unroll 4
        for (int c = half; c < nact; c += 2)
            a += g_pacc[((size_t)b*CHUNKS + c)*H + t] * es[c];
        part[tid] = a;
    }
    __syncthreads();
    if (tid < 128) {
        cp[t] = (part[t] + part[t+128]) / L;
        xsm[t] = g_x[b*H + t];
    }
    __syncthreads();

    {
        float cv = 0.f;
        int i0 = half*64;
#pragma unroll 8
        for (int i = i0; i < i0 + 64; i++) cv += cp[i] * Wv[i*H + t];
        part[tid] = cv;
    }
    __syncthreads();
    if (tid < 128) ctxs[t] = part[t] + part[t+128] + bv[t];
    __syncthreads();

    {
        float hm = 0.f;
        if (half == 0) {
#pragma unroll 8
            for (int i = 0; i < 128; i++) hm += xsm[i] * Wmix[i*H + t];
        } else {
#pragma unroll 8
            for (int i = 0; i < 128; i++) hm += ctxs[i] * Wmix[(H+i)*H + t];
        }
        part[tid] = hm;
    }
    __syncthreads();

    float hv = 0.f;
    if (tid < 128) {
        hv = tanhf(part[t] + part[t+128] + bmix[t]);
        red[t] = hv;
    }
    __syncthreads();
    for (int o = 64; o > 0; o >>= 1) {
        if (tid < o) red[tid] += red[tid+o];
        __syncthreads();
    }
    float mu = red[0] * (1.f/128.f);
    __syncthreads();
    float dv = hv - mu;
    if (tid < 128) red[t] = dv*dv;
    __syncthreads();
    for (int o = 64; o > 0; o >>= 1) {
        if (tid < o) red[tid] += red[tid+o];
        __syncthreads();
    }
    float var = red[0] * (1.f/128.f);

    if (tid < 128)
        g_hln[b*H + t] = dv * rsqrtf(var + 1e-6f) * lns[t] + lnb[t];
}

// ==== K4: logits = h_ln @ Wout + bout; 2 cols (c, c+256) x 16 batches =====
__global__ __launch_bounds__(256, 4) void k_logits(
    const float* __restrict__ Wout, const float* __restrict__ bout,
    float* __restrict__ out)
{
    __shared__ ull hsu[H*8];
    int tid = threadIdx.x;
    int bq = blockIdx.y;

    if (blockIdx.x == 0 && bq == 0 && tid == 0) g_done = 0;

    float* hsf = (float*)hsu;
    for (int idx = tid; idx < 16*H; idx += 256) {
        int k = idx >> 4, bb = idx & 15;
        hsf[k*16 + bb] = g_hln[(bq*16 + bb)*H + k];
    }
    __syncthreads();

    int base = blockIdx.x * 512;
    int ca = base + tid;
    int cb = ca + 256;
    int ca_ok = (ca < V), cb_ok = (cb < V);
    int ca_c = ca_ok ? ca : (V-1);
    int cb_c = cb_ok ? cb : (V-1);

    ull acc0[8], acc1[8];
#pragma unroll
    for (int i = 0; i < 8; i++) { acc0[i] = 0ULL; acc1[i] = 0ULL; }

#pragma unroll 4
    for (int k = 0; k < H; k++) {
        float wa = Wout[(size_t)k*V + ca_c];
        float wb = Wout[(size_t)k*V + cb_c];
        ull w2a = bcast2(wa);
        ull w2b = bcast2(wb);
        const ulonglong2* hp = (const ulonglong2*)(hsu + k*8);
#pragma unroll
        for (int p = 0; p < 4; p++) {
            ulonglong2 hv = hp[p];
            acc0[2*p]   = fma2(hv.x, w2a, acc0[2*p]);
            acc0[2*p+1] = fma2(hv.y, w2a, acc0[2*p+1]);
            acc1[2*p]   = fma2(hv.x, w2b, acc1[2*p]);
            acc1[2*p+1] = fma2(hv.y, w2b, acc1[2*p+1]);
        }
    }

    if (ca_ok) {
        float bo = bout[ca_c];
#pragma unroll
        for (int p = 0; p < 8; p++) {
            float f0, f1;
            asm("mov.b64 {%0, %1}, %2;" : "=f"(f0), "=f"(f1) : "l"(acc0[p]));
            int b0r = bq*16 + 2*p;
            out[(size_t)b0r*V + ca]     = f0 + bo;
            out[(size_t)(b0r+1)*V + ca] = f1 + bo;
        }
    }
    if (cb_ok) {
        float bo = bout[cb_c];
#pragma unroll
        for (int p = 0; p < 8; p++) {
            float f0, f1;
            asm("mov.b64 {%0, %1}, %2;" : "=f"(f0), "=f"(f1) : "l"(acc1[p]));
            int b0r = bq*16 + 2*p;
            out[(size_t)b0r*V + cb]     = f0 + bo;
            out[(size_t)(b0r+1)*V + cb] = f1 + bo;
        }
    }
}

// ==========================================================================
extern "C" void kernel_launch(void* const* d_in, const int* in_sizes, int n_in,
                              void* d_out, int out_size)
{
    const int*   token_id = (const int*)  d_in[0];
    const float* c0       = (const float*)d_in[1];
    const float* h0       = (const float*)d_in[2];
    const float* attn_mem = (const float*)d_in[3];
    const int*   step_p   = (const int*)  d_in[4];
    const float* emb      = (const float*)d_in[5];
    const float* Wi       = (const float*)d_in[6];
    const float* Uh       = (const float*)d_in[7];
    const float* bL       = (const float*)d_in[8];
    const float* Wq       = (const float*)d_in[9];
    const float* bq       = (const float*)d_in[10];
    const float* Wk       = (const float*)d_in[11];
    const float* bk       = (const float*)d_in[12];
    const float* Wv       = (const float*)d_in[13];
    const float* bv       = (const float*)d_in[14];
    const float* Wmix     = (const float*)d_in[15];
    const float* bmix     = (const float*)d_in[16];
    const float* lns      = (const float*)d_in[17];
    const float* lnb      = (const float*)d_in[18];
    const float* Wout     = (const float*)d_in[19];
    const float* bout     = (const float*)d_in[20];
    float* out = (float*)d_out;

    static int smem_set = 0;
    if (!smem_set) {
        cudaFuncSetAttribute(k_mega, cudaFuncAttributeMaxDynamicSharedMemorySize,
                             SMEM_BYTES);
        smem_set = 1;
    }

    k_mega<<<32 + NWORK, 256, SMEM_BYTES>>>(attn_mem, step_p, token_id, c0, h0,
                                            emb, Wi, Uh, bL, Wq, bq, Wk, bk, out);
    k_reduce_mix<<<B, 256>>>(step_p, Wv, bv, Wmix, bmix, lns, lnb);
    dim3 g4((V + 511)/512, 4);
    k_logits<<<g4, 256>>>(Wout, bout, out);
}